// round 14
// baseline (speedup 1.0000x reference)
#include <cuda_runtime.h>
#include <cstdint>
#include <cmath>

#define BB 512
#define NN 1000
#define CC 50
#define CCP 51              // pitch for transposed cluster tile (odd -> conflict-free)
#define EE 128
#define HH 8
#define DD 16
#define SPLIT 8
#define NPS (NN/SPLIT)
#define NEGV (-1e9f)
// prep rows: 384 Wqf + 128 WkfT + 128 Wvf + 128 WoKs + 64 qcd-groups = 832
#define PREP_W   (6*EE)          // 768
#define PREP_ALL (PREP_W + 64)   // 832  (fits in 2 planes of 512)

// scratch (no cudaMalloc allowed)
__device__ float g_part[BB*SPLIT*2*EE];   // [b][split][{mask, mask|cmask}][e]
__device__ float g_Wqf [3*EE*EE];         // Wq @ mha_Wq   (384 x 128), [i][j]
__device__ float g_WkfT[EE*EE];           // (Wk @ mha_Wk)^T : [j][e]
__device__ float g_Wvf [EE*EE];           // Wv @ mha_Wv    : [e][j]
__device__ float g_WoKs[EE*EE];           // Wo @ Wks^T     : [j][e]
__device__ float g_qcd [BB*EE];           // (cur@W1 + depot@W2)@mWq per batch

// ---------------------------------------------------------------------------
// Kernel 1: masked reduction (simple predicated loop — measured-best form)
// + prep planes: fused weights AND batch-tiled qcd (8 batches per block).
// grid (BB, SPLIT+2), 128 threads.
// ---------------------------------------------------------------------------
__global__ void __launch_bounds__(128) k_pre(
    const float* __restrict__ nodes,
    const int* __restrict__ mask, const int* __restrict__ cmask,
    const float* __restrict__ Wq, const float* __restrict__ Wk,
    const float* __restrict__ Wv, const float* __restrict__ Wks,
    const float* __restrict__ Wo,
    const float* __restrict__ mWq, const float* __restrict__ mWk,
    const float* __restrict__ mWv,
    const float* __restrict__ cur, const float* __restrict__ depot)
{
    const int b = blockIdx.x, y = blockIdx.y, t = threadIdx.x;
    const int warp = t >> 5, lane = t & 31;

    if (y >= SPLIT) {
        // ---- prep planes ----
        int fr = (y - SPLIT)*BB + b;
        if (fr >= PREP_ALL) return;
        if (fr < 3*EE) {
            const float* a_ = Wq + fr*EE;
            float s0=0.f,s1=0.f,s2=0.f,s3=0.f;
            #pragma unroll 8
            for (int e = 0; e < EE; e += 4) {
                s0 += a_[e  ] * mWq[(e  )*EE + t];
                s1 += a_[e+1] * mWq[(e+1)*EE + t];
                s2 += a_[e+2] * mWq[(e+2)*EE + t];
                s3 += a_[e+3] * mWq[(e+3)*EE + t];
            }
            g_Wqf[fr*EE + t] = (s0+s1)+(s2+s3);
        } else if (fr < 4*EE) {
            const int e0 = fr - 3*EE;
            const float* a_ = Wk + e0*EE;
            float s0=0.f,s1=0.f,s2=0.f,s3=0.f;
            #pragma unroll 8
            for (int x = 0; x < EE; x += 4) {
                s0 += a_[x  ] * mWk[(x  )*EE + t];
                s1 += a_[x+1] * mWk[(x+1)*EE + t];
                s2 += a_[x+2] * mWk[(x+2)*EE + t];
                s3 += a_[x+3] * mWk[(x+3)*EE + t];
            }
            g_WkfT[t*EE + e0] = (s0+s1)+(s2+s3);   // transposed
        } else if (fr < 5*EE) {
            const int e0 = fr - 4*EE;
            const float* a_ = Wv + e0*EE;
            float s0=0.f,s1=0.f,s2=0.f,s3=0.f;
            #pragma unroll 8
            for (int x = 0; x < EE; x += 4) {
                s0 += a_[x  ] * mWv[(x  )*EE + t];
                s1 += a_[x+1] * mWv[(x+1)*EE + t];
                s2 += a_[x+2] * mWv[(x+2)*EE + t];
                s3 += a_[x+3] * mWv[(x+3)*EE + t];
            }
            g_Wvf[e0*EE + t] = (s0+s1)+(s2+s3);
        } else if (fr < 6*EE) {
            // WoKs[j][e] = sum_f Wo[j][f] * Wks[e][f]  — tiled, coalesced
            const int j = fr - 5*EE;
            __shared__ float sWo[EE];
            __shared__ float sTile[32][EE + 1];
            sWo[t] = Wo[j*EE + t];
            float acc = 0.f;
            for (int f0 = 0; f0 < EE; f0 += 32) {
                __syncthreads();
                #pragma unroll 8
                for (int k = 0; k < 32; k++) {
                    int e = warp*32 + k;
                    sTile[lane][e] = Wks[e*EE + f0 + lane];   // coalesced
                }
                __syncthreads();
                #pragma unroll 8
                for (int fi = 0; fi < 32; fi++)
                    acc += sWo[f0 + fi] * sTile[fi][t];       // conflict-free
            }
            g_WoKs[j*EE + t] = acc;
        } else {
            // qcd for 8 batches per block: weight elements loaded once,
            // reused across all 8 batches (register-tiled over batch).
            const int g8 = (fr - PREP_W) * 8;      // first batch of group
            __shared__ float sCur[8][EE], sDep[8][EE], sTmp[8][EE];
            #pragma unroll
            for (int nb = 0; nb < 8; nb++) {
                sCur[nb][t] = cur  [(g8 + nb)*EE + t];
                sDep[nb][t] = depot[(g8 + nb)*EE + t];
            }
            __syncthreads();
            // stage 1: tmp[nb][e=t] = sum_x cur*Wq[128+x][e] + dep*Wq[256+x][e]
            {
                float acc[8];
                #pragma unroll
                for (int nb = 0; nb < 8; nb++) acc[nb] = 0.f;
                for (int x = 0; x < EE; x++) {
                    float w1 = Wq[(EE   + x)*EE + t];
                    float w2 = Wq[(2*EE + x)*EE + t];
                    #pragma unroll
                    for (int nb = 0; nb < 8; nb++)
                        acc[nb] += sCur[nb][x]*w1 + sDep[nb][x]*w2;
                }
                #pragma unroll
                for (int nb = 0; nb < 8; nb++) sTmp[nb][t] = acc[nb];
            }
            __syncthreads();
            // stage 2: qcd[nb][j=t] = sum_e tmp[nb][e]*mWq[e][j]
            {
                float acc[8];
                #pragma unroll
                for (int nb = 0; nb < 8; nb++) acc[nb] = 0.f;
                for (int e = 0; e < EE; e++) {
                    float w = mWq[e*EE + t];
                    #pragma unroll
                    for (int nb = 0; nb < 8; nb++)
                        acc[nb] += sTmp[nb][e] * w;
                }
                #pragma unroll
                for (int nb = 0; nb < 8; nb++)
                    g_qcd[(g8 + nb)*EE + t] = acc[nb];
            }
        }
        return;
    }

    // ---- reduction plane: rows [y*NPS, (y+1)*NPS) of batch b ----
    __shared__ uint8_t sM[NPS], sC[NPS];
    __shared__ float4  sR0[4][32], sR1[4][32];

    const int* m  = mask  + b*NN + y*NPS;
    const int* cm = cmask + b*NN + y*NPS;
    if (t < NPS) {
        sM[t] = (uint8_t)(m[t]  != 0);
        sC[t] = (uint8_t)(cm[t] != 0);
    }
    __syncthreads();

    const float4* base = (const float4*)(nodes + ((size_t)b*NN + (size_t)y*NPS)*EE);

    float4 a0 = make_float4(0.f,0.f,0.f,0.f);
    float4 a1 = make_float4(0.f,0.f,0.f,0.f);
    for (int r = warp; r < NPS; r += 4) {
        if (!sM[r]) {                        // warp-uniform: skip masked rows
            float4 v = __ldg(base + r*32 + lane);
            a0.x += v.x; a0.y += v.y; a0.z += v.z; a0.w += v.w;
            if (!sC[r]) { a1.x += v.x; a1.y += v.y; a1.z += v.z; a1.w += v.w; }
        }
    }
    sR0[warp][lane] = a0;
    sR1[warp][lane] = a1;
    __syncthreads();

    const float* p0 = (const float*)sR0;
    const float* p1 = (const float*)sR1;
    float s0 = p0[t] + p0[128 + t] + p0[256 + t] + p0[384 + t];
    float s1 = p1[t] + p1[128 + t] + p1[256 + t] + p1[384 + t];
    int idx = (b*SPLIT + y)*2*EE + t;
    g_part[idx]      = s0;
    g_part[idx + EE] = s1;
}

// ---------------------------------------------------------------------------
// Kernel 2: math chain per batch. 256 threads/block. (verified 33.5us form)
// ---------------------------------------------------------------------------
__global__ void __launch_bounds__(256) k_main(
    const float* __restrict__ depot, const float* __restrict__ CE,
    const float* __restrict__ cur,   const float* __restrict__ augc,
    const float* __restrict__ gein,
    const int* __restrict__ isnew, const int* __restrict__ vcm_g,
    const int* __restrict__ guid_in, float* __restrict__ out)
{
    const int b = blockIdx.x, t = threadIdx.x;
    const int t2 = t & 127, half = t >> 7;
    const int warp = t >> 5, lane = t & 31;

    __shared__ float sCET[EE*CCP];     // transposed cluster embeddings
    __shared__ float sCtx[3*EE];
    __shared__ float sUC[EE];
    __shared__ float sQcd[EE];
    __shared__ float sP2[2][EE];       // split-K partials (reused per stage)
    __shared__ float sQ[EE];
    __shared__ float sKQ[HH*EE];
    __shared__ float sSc[HH*CC];
    __shared__ float sAt[HH*CC];
    __shared__ float sAce[HH*EE];
    __shared__ float sGl[EE];
    __shared__ float sW2[EE];
    __shared__ float sLgP[4][CC];
    __shared__ float sLg[CC];
    __shared__ int   sVcm[CC];
    __shared__ float sMax, sLse;
    __shared__ int   sArg;

    // ---- load cluster embeddings transposed; half owns 25 c's, e = t2 ----
    {
        const float* src = CE + (size_t)b*CC*EE;
        #pragma unroll
        for (int cc = 0; cc < 25; cc++) {
            int c = half*25 + cc;
            sCET[t2*CCP + c] = src[c*EE + t2];
        }
    }

    // ---- combine reduction partials: half 0 -> um, half 1 -> uc ----
    {
        float a = 0.f;
        #pragma unroll
        for (int s = 0; s < SPLIT; s++)
            a += g_part[(b*SPLIT + s)*2*EE + half*EE + t2];
        a *= (1.f/NN);
        if (half == 0) sCtx[t2] = a; else sUC[t2] = a;
    }
    if (half == 0) { sCtx[EE + t2] = cur[b*EE + t2]; sQcd[t2] = g_qcd[b*EE + t2]; }
    else           sCtx[2*EE + t2] = depot[b*EE + t2];
    if (t < CC) sVcm[t] = (vcm_g[b*CC + t] != 0);
    __syncthreads();

    if (t == 0) {                      // vcm[0] = !all(vcm[1:])
        int all = 1;
        for (int c = 1; c < CC; c++) all &= (sVcm[c] != 0);
        sVcm[0] = !all;
    }

    // ---- q = um@W0 + qcd; split-K over halves (64 MACs each, 4 accs) ----
    {
        const int i0 = half*64;
        float a0=0.f,a1=0.f,a2=0.f,a3=0.f;
        #pragma unroll 4
        for (int i = 0; i < 64; i += 4) {
            a0 += sCtx[i0+i  ] * g_Wqf[(i0+i  )*EE + t2];
            a1 += sCtx[i0+i+1] * g_Wqf[(i0+i+1)*EE + t2];
            a2 += sCtx[i0+i+2] * g_Wqf[(i0+i+2)*EE + t2];
            a3 += sCtx[i0+i+3] * g_Wqf[(i0+i+3)*EE + t2];
        }
        sP2[half][t2] = (a0+a1)+(a2+a3);
    }
    __syncthreads();
    if (half == 0) sQ[t2] = sP2[0][t2] + sP2[1][t2] + sQcd[t2];
    __syncthreads();

    // ---- kq[h][e]: 1024 outputs over 256 threads (4 each), 16 MACs ----
    #pragma unroll
    for (int k = 0; k < 4; k++) {
        int idx = t + 256*k;
        int h = idx >> 7, e = idx & 127;
        float a0=0.f,a1=0.f;
        #pragma unroll
        for (int d = 0; d < DD; d += 2) {
            a0 += sQ[h*DD + d  ] * g_WkfT[(h*DD + d  )*EE + e];
            a1 += sQ[h*DD + d+1] * g_WkfT[(h*DD + d+1)*EE + e];
        }
        sKQ[h*EE + e] = a0 + a1;
    }
    __syncthreads();

    // ---- scores: 400 outputs, 128 MACs, 4 accs ----
    for (int idx = t; idx < HH*CC; idx += 256) {
        int h = idx / CC, c = idx % CC;
        float a0=0.f,a1=0.f,a2=0.f,a3=0.f;
        #pragma unroll 4
        for (int e = 0; e < EE; e += 4) {
            a0 += sCET[(e  )*CCP + c] * sKQ[h*EE + e  ];
            a1 += sCET[(e+1)*CCP + c] * sKQ[h*EE + e+1];
            a2 += sCET[(e+2)*CCP + c] * sKQ[h*EE + e+2];
            a3 += sCET[(e+3)*CCP + c] * sKQ[h*EE + e+3];
        }
        float a = ((a0+a1)+(a2+a3)) * 0.25f;   // 1/sqrt(16)
        if (sVcm[c]) a = NEGV;
        sSc[h*CC + c] = a;
    }
    __syncthreads();

    // ---- softmax: warp h owns head h ----
    {
        int h = warp;
        float v0 = sSc[h*CC + lane];
        float v1 = (lane < CC-32) ? sSc[h*CC + lane + 32] : -3e38f;
        float mx = fmaxf(v0, v1);
        #pragma unroll
        for (int o = 16; o > 0; o >>= 1)
            mx = fmaxf(mx, __shfl_xor_sync(0xffffffffu, mx, o));
        float e0 = expf(v0 - mx);
        float e1 = (lane < CC-32) ? expf(v1 - mx) : 0.f;
        float sm = e0 + e1;
        #pragma unroll
        for (int o = 16; o > 0; o >>= 1)
            sm += __shfl_xor_sync(0xffffffffu, sm, o);
        float inv = 1.f / sm;
        sAt[h*CC + lane] = e0 * inv;
        if (lane < CC-32) sAt[h*CC + lane + 32] = e1 * inv;
    }
    __syncthreads();

    // ---- a_ce[h][e]: 1024 outputs over 256 threads, 50 MACs, 2 accs ----
    #pragma unroll
    for (int k = 0; k < 4; k++) {
        int idx = t + 256*k;
        int h = idx >> 7, e = idx & 127;
        float a0=0.f,a1=0.f;
        #pragma unroll 5
        for (int c = 0; c < CC; c += 2) {
            a0 += sAt[h*CC + c  ] * sCET[e*CCP + c  ];
            a1 += sAt[h*CC + c+1] * sCET[e*CCP + c+1];
        }
        sAce[h*EE + e] = a0 + a1;
    }
    __syncthreads();

    // ---- glimpse[j=t2]: 128-MAC split-K over halves (h = j/16) ----
    {
        int h = t2 / DD;
        const int e0 = half*64;
        float a0=0.f,a1=0.f,a2=0.f,a3=0.f;
        #pragma unroll 4
        for (int e = 0; e < 64; e += 4) {
            a0 += sAce[h*EE + e0+e  ] * g_Wvf[(e0+e  )*EE + t2];
            a1 += sAce[h*EE + e0+e+1] * g_Wvf[(e0+e+1)*EE + t2];
            a2 += sAce[h*EE + e0+e+2] * g_Wvf[(e0+e+2)*EE + t2];
            a3 += sAce[h*EE + e0+e+3] * g_Wvf[(e0+e+3)*EE + t2];
        }
        sP2[half][t2] = (a0+a1)+(a2+a3);
    }
    __syncthreads();
    if (half == 0) sGl[t2] = sP2[0][t2] + sP2[1][t2];
    __syncthreads();

    // ---- w2[e=t2] = sum_j gl[j] * WoKs[j][e]: split-K over halves ----
    {
        const int j0 = half*64;
        float a0=0.f,a1=0.f,a2=0.f,a3=0.f;
        #pragma unroll 4
        for (int j = 0; j < 64; j += 4) {
            a0 += sGl[j0+j  ] * g_WoKs[(j0+j  )*EE + t2];
            a1 += sGl[j0+j+1] * g_WoKs[(j0+j+1)*EE + t2];
            a2 += sGl[j0+j+2] * g_WoKs[(j0+j+2)*EE + t2];
            a3 += sGl[j0+j+3] * g_WoKs[(j0+j+3)*EE + t2];
        }
        sP2[half][t2] = (a0+a1)+(a2+a3);
    }
    __syncthreads();
    if (half == 0) sW2[t2] = sP2[0][t2] + sP2[1][t2];
    __syncthreads();

    // ---- logit[c]: 50 outputs, split over 4 quarters of e ----
    {
        int c = t & 63, q4 = t >> 6;
        if (c < CC) {
            const int e0 = q4*32;
            float a0=0.f,a1=0.f;
            #pragma unroll 4
            for (int e = 0; e < 32; e += 2) {
                a0 += sCET[(e0+e  )*CCP + c] * sW2[e0+e  ];
                a1 += sCET[(e0+e+1)*CCP + c] * sW2[e0+e+1];
            }
            sLgP[q4][c] = a0 + a1;
        }
    }
    __syncthreads();
    if (t < CC) {
        float a = (sLgP[0][t] + sLgP[1][t]) + (sLgP[2][t] + sLgP[3][t]);
        a *= 0.08838834764831845f;     // 1/sqrt(128)
        a = tanhf(a) * 10.f;
        if (sVcm[t]) a = NEGV;
        sLg[t] = a;
    }
    __syncthreads();

    // ---- argmax (first-index ties) + logsumexp, warp 0 via shfl ----
    if (warp == 0) {
        float v0 = sLg[lane];
        float v1 = (lane < CC-32) ? sLg[lane + 32] : -3e38f;
        float v = v0; int ix = lane;
        if (v1 > v) { v = v1; ix = lane + 32; }
        #pragma unroll
        for (int o = 16; o > 0; o >>= 1) {
            float ov = __shfl_xor_sync(0xffffffffu, v, o);
            int   oi = __shfl_xor_sync(0xffffffffu, ix, o);
            if (ov > v || (ov == v && oi < ix)) { v = ov; ix = oi; }
        }
        float mx = v;
        float sm = expf(v0 - mx) + ((lane < CC-32) ? expf(v1 - mx) : 0.f);
        #pragma unroll
        for (int o = 16; o > 0; o >>= 1)
            sm += __shfl_xor_sync(0xffffffffu, sm, o);
        if (lane == 0) { sMax = mx; sLse = logf(sm); sArg = ix; }
    }
    __syncthreads();

    const int  guid = sArg;
    const bool isn  = isnew[b] != 0;
    const float ge  = sCET[t2*CCP + guid];

    const size_t OFF1 = (size_t)BB*4*EE;            // guid_embed_out
    const size_t OFF2 = OFF1 + (size_t)BB*EE;       // guid_out
    const size_t OFF3 = OFF2 + BB;                  // clu_prob

    float* ao = out + (size_t)b*4*EE;
    const float* ac = augc + (size_t)b*4*EE;
    if (half == 0) {
        ao[t2]        = isn ? sUC[t2]          : ac[t2];
        ao[2*EE + t2] = isn ? ge               : ac[2*EE + t2];
        out[OFF1 + (size_t)b*EE + t2] = isn ? ge : gein[b*EE + t2];
    } else {
        ao[EE + t2]   = isn ? sCtx[EE + t2]    : ac[EE + t2];
        ao[3*EE + t2] = isn ? sCtx[2*EE + t2]  : ac[3*EE + t2];
    }
    if (t == 0) out[OFF2 + b] = (float)(isn ? guid : guid_in[b]);
    if (t < CC) out[OFF3 + (size_t)b*CC + t] = isn ? (sLg[t] - sMax - sLse) : 0.f;
}

// ---------------------------------------------------------------------------
extern "C" void kernel_launch(void* const* d_in, const int* in_sizes, int n_in,
                              void* d_out, int out_size) {
    const float* depot = (const float*)d_in[0];
    const float* CE    = (const float*)d_in[1];
    const float* cur   = (const float*)d_in[2];
    const float* nodes = (const float*)d_in[3];
    const float* augc  = (const float*)d_in[4];
    const float* gein  = (const float*)d_in[5];
    const float* Wq    = (const float*)d_in[6];
    const float* Wk    = (const float*)d_in[7];
    const float* Wv    = (const float*)d_in[8];
    const float* Wks   = (const float*)d_in[9];
    const float* mWq   = (const float*)d_in[10];
    const float* mWk   = (const float*)d_in[11];
    const float* mWv   = (const float*)d_in[12];
    const float* Wo    = (const float*)d_in[13];
    const int* isnew   = (const int*)d_in[14];   // bool -> int32
    const int* mask    = (const int*)d_in[15];   // bool -> int32
    const int* cmask   = (const int*)d_in[16];   // bool -> int32
    const int* vcm     = (const int*)d_in[17];   // bool -> int32
    const int* guid    = (const int*)d_in[18];
    // d_in[19] = step (unused)

    dim3 gr(BB, SPLIT + 2);   // 8 reduce planes + 2 prep planes (832 rows)
    k_pre<<<gr, 128>>>(nodes, mask, cmask, Wq, Wk, Wv, Wks, Wo,
                       mWq, mWk, mWv, cur, depot);
    k_main<<<BB, 256>>>(depot, CE, cur, augc, gein, isnew, vcm, guid,
                        (float*)d_out);
}

// round 15
// speedup vs baseline: 1.1249x; 1.1249x over previous
#include <cuda_runtime.h>
#include <cstdint>
#include <cmath>

#define BB 512
#define NN 1000
#define CC 50
#define CCP 51              // pitch for transposed cluster tile (odd -> conflict-free)
#define EE 128
#define HH 8
#define DD 16
#define SPLIT 8
#define NPS (NN/SPLIT)
#define NEGV (-1e9f)
// prep rows: 384 Wqf + 128 WkfT + 128 Wvf + 128 WoKs + 128 qcd-groups(4 each) = 896
#define PREP_W   (6*EE)           // 768
#define PREP_ALL (PREP_W + 128)   // 896  (fits in 2 planes of 512)

// scratch (no cudaMalloc allowed)
__device__ float g_part[BB*SPLIT*2*EE];   // [b][split][{mask, mask|cmask}][e]
__device__ float g_Wqf [3*EE*EE];         // Wq @ mha_Wq   (384 x 128), [i][j]
__device__ float g_WkfT[EE*EE];           // (Wk @ mha_Wk)^T : [j][e]
__device__ float g_Wvf [EE*EE];           // Wv @ mha_Wv    : [e][j]
__device__ float g_WoKs[EE*EE];           // Wo @ Wks^T     : [j][e]
__device__ float g_qcd [BB*EE];           // (cur@W1 + depot@W2)@mWq per batch

// ---------------------------------------------------------------------------
// Kernel 1: prep planes FIRST (y=0,1 — scheduled early, hidden under the
// DRAM stream), then reduction planes (y=2..9). ONE aliased smem buffer so
// the per-branch shared arrays union instead of summing (occupancy!).
// grid (BB, SPLIT+2), 128 threads.
// ---------------------------------------------------------------------------
__global__ void __launch_bounds__(128, 12) k_pre(
    const float* __restrict__ nodes,
    const int* __restrict__ mask, const int* __restrict__ cmask,
    const float* __restrict__ Wq, const float* __restrict__ Wk,
    const float* __restrict__ Wv, const float* __restrict__ Wks,
    const float* __restrict__ Wo,
    const float* __restrict__ mWq, const float* __restrict__ mWk,
    const float* __restrict__ mWv,
    const float* __restrict__ cur, const float* __restrict__ depot)
{
    const int b = blockIdx.x, y = blockIdx.y, t = threadIdx.x;
    const int warp = t >> 5, lane = t & 31;

    __shared__ __align__(16) char sBuf[12544];   // union for ALL planes

    if (y < 2) {
        // ---- prep planes (early-scheduled) ----
        int fr = y*BB + b;
        if (fr >= PREP_ALL) return;
        if (fr < 3*EE) {
            const float* a_ = Wq + fr*EE;
            float s0=0.f,s1=0.f,s2=0.f,s3=0.f;
            #pragma unroll 8
            for (int e = 0; e < EE; e += 4) {
                s0 += a_[e  ] * mWq[(e  )*EE + t];
                s1 += a_[e+1] * mWq[(e+1)*EE + t];
                s2 += a_[e+2] * mWq[(e+2)*EE + t];
                s3 += a_[e+3] * mWq[(e+3)*EE + t];
            }
            g_Wqf[fr*EE + t] = (s0+s1)+(s2+s3);
        } else if (fr < 4*EE) {
            const int e0 = fr - 3*EE;
            const float* a_ = Wk + e0*EE;
            float s0=0.f,s1=0.f,s2=0.f,s3=0.f;
            #pragma unroll 8
            for (int x = 0; x < EE; x += 4) {
                s0 += a_[x  ] * mWk[(x  )*EE + t];
                s1 += a_[x+1] * mWk[(x+1)*EE + t];
                s2 += a_[x+2] * mWk[(x+2)*EE + t];
                s3 += a_[x+3] * mWk[(x+3)*EE + t];
            }
            g_WkfT[t*EE + e0] = (s0+s1)+(s2+s3);   // transposed
        } else if (fr < 5*EE) {
            const int e0 = fr - 4*EE;
            const float* a_ = Wv + e0*EE;
            float s0=0.f,s1=0.f,s2=0.f,s3=0.f;
            #pragma unroll 8
            for (int x = 0; x < EE; x += 4) {
                s0 += a_[x  ] * mWv[(x  )*EE + t];
                s1 += a_[x+1] * mWv[(x+1)*EE + t];
                s2 += a_[x+2] * mWv[(x+2)*EE + t];
                s3 += a_[x+3] * mWv[(x+3)*EE + t];
            }
            g_Wvf[e0*EE + t] = (s0+s1)+(s2+s3);
        } else if (fr < 6*EE) {
            // WoKs[j][e=t] = sum_f Wo[j][f] * Wks[e][f], 16-f smem tiles
            const int j = fr - 5*EE;
            float* sWo = (float*)sBuf;                          // 512 B
            float (*sTile)[EE + 1] = (float(*)[EE + 1])(sBuf + 512); // 16x129
            sWo[t] = Wo[j*EE + t];
            float acc = 0.f;
            for (int f0 = 0; f0 < EE; f0 += 16) {
                __syncthreads();
                // warp w loads rows e = w*32..+31; lanes 0..15 carry f
                #pragma unroll 8
                for (int k = 0; k < 32; k++) {
                    int e = warp*32 + k;
                    if (lane < 16) sTile[lane][e] = Wks[e*EE + f0 + lane];
                }
                __syncthreads();
                #pragma unroll
                for (int fi = 0; fi < 16; fi++)
                    acc += sWo[f0 + fi] * sTile[fi][t];       // conflict-free
            }
            g_WoKs[j*EE + t] = acc;
        } else {
            // qcd for 4 batches per block, weights loaded once, 2-way unroll
            const int g4 = (fr - PREP_W) * 4;      // first batch of group
            float (*sCur)[EE] = (float(*)[EE])(sBuf);          // 2 KB
            float (*sDep)[EE] = (float(*)[EE])(sBuf + 2048);   // 2 KB
            float (*sTmp)[EE] = (float(*)[EE])(sBuf + 4096);   // 2 KB
            #pragma unroll
            for (int nb = 0; nb < 4; nb++) {
                sCur[nb][t] = cur  [(g4 + nb)*EE + t];
                sDep[nb][t] = depot[(g4 + nb)*EE + t];
            }
            __syncthreads();
            // stage 1: tmp[nb][e=t] = sum_x cur*Wq[128+x][e] + dep*Wq[256+x][e]
            {
                float acc[4] = {0.f,0.f,0.f,0.f};
                for (int x = 0; x < EE; x += 2) {
                    float w1a = Wq[(EE   + x  )*EE + t];
                    float w2a = Wq[(2*EE + x  )*EE + t];
                    float w1b = Wq[(EE   + x+1)*EE + t];
                    float w2b = Wq[(2*EE + x+1)*EE + t];
                    #pragma unroll
                    for (int nb = 0; nb < 4; nb++) {
                        acc[nb] += sCur[nb][x  ]*w1a + sDep[nb][x  ]*w2a;
                        acc[nb] += sCur[nb][x+1]*w1b + sDep[nb][x+1]*w2b;
                    }
                }
                #pragma unroll
                for (int nb = 0; nb < 4; nb++) sTmp[nb][t] = acc[nb];
            }
            __syncthreads();
            // stage 2: qcd[nb][j=t] = sum_e tmp[nb][e]*mWq[e][j]
            {
                float acc[4] = {0.f,0.f,0.f,0.f};
                for (int e = 0; e < EE; e += 2) {
                    float wa = mWq[(e  )*EE + t];
                    float wb = mWq[(e+1)*EE + t];
                    #pragma unroll
                    for (int nb = 0; nb < 4; nb++)
                        acc[nb] += sTmp[nb][e]*wa + sTmp[nb][e+1]*wb;
                }
                #pragma unroll
                for (int nb = 0; nb < 4; nb++)
                    g_qcd[(g4 + nb)*EE + t] = acc[nb];
            }
        }
        return;
    }

    // ---- reduction plane s = y-2: rows [s*NPS, (s+1)*NPS) of batch b ----
    const int s = y - 2;
    uint8_t* sM  = (uint8_t*)sBuf;                 // 128 B
    uint8_t* sC  = (uint8_t*)sBuf + 128;           // 128 B
    float4 (*sR0)[32] = (float4(*)[32])(sBuf + 256);          // 2 KB
    float4 (*sR1)[32] = (float4(*)[32])(sBuf + 256 + 2048);   // 2 KB

    const int* m  = mask  + b*NN + s*NPS;
    const int* cm = cmask + b*NN + s*NPS;
    if (t < NPS) {
        sM[t] = (uint8_t)(m[t]  != 0);
        sC[t] = (uint8_t)(cm[t] != 0);
    }
    __syncthreads();

    const float4* base = (const float4*)(nodes + ((size_t)b*NN + (size_t)s*NPS)*EE);

    float4 a0 = make_float4(0.f,0.f,0.f,0.f);
    float4 a1 = make_float4(0.f,0.f,0.f,0.f);
    for (int r = warp; r < NPS; r += 4) {
        if (!sM[r]) {                        // warp-uniform: skip masked rows
            float4 v = __ldg(base + r*32 + lane);
            a0.x += v.x; a0.y += v.y; a0.z += v.z; a0.w += v.w;
            if (!sC[r]) { a1.x += v.x; a1.y += v.y; a1.z += v.z; a1.w += v.w; }
        }
    }
    sR0[warp][lane] = a0;
    sR1[warp][lane] = a1;
    __syncthreads();

    const float* p0 = (const float*)sR0;
    const float* p1 = (const float*)sR1;
    float s0 = p0[t] + p0[128 + t] + p0[256 + t] + p0[384 + t];
    float s1 = p1[t] + p1[128 + t] + p1[256 + t] + p1[384 + t];
    int idx = (b*SPLIT + s)*2*EE + t;
    g_part[idx]      = s0;
    g_part[idx + EE] = s1;
}

// ---------------------------------------------------------------------------
// Kernel 2: math chain per batch. 256 threads/block. (verified 33.5us form —
// byte-identical to R13/R14)
// ---------------------------------------------------------------------------
__global__ void __launch_bounds__(256) k_main(
    const float* __restrict__ depot, const float* __restrict__ CE,
    const float* __restrict__ cur,   const float* __restrict__ augc,
    const float* __restrict__ gein,
    const int* __restrict__ isnew, const int* __restrict__ vcm_g,
    const int* __restrict__ guid_in, float* __restrict__ out)
{
    const int b = blockIdx.x, t = threadIdx.x;
    const int t2 = t & 127, half = t >> 7;
    const int warp = t >> 5, lane = t & 31;

    __shared__ float sCET[EE*CCP];     // transposed cluster embeddings
    __shared__ float sCtx[3*EE];
    __shared__ float sUC[EE];
    __shared__ float sQcd[EE];
    __shared__ float sP2[2][EE];       // split-K partials (reused per stage)
    __shared__ float sQ[EE];
    __shared__ float sKQ[HH*EE];
    __shared__ float sSc[HH*CC];
    __shared__ float sAt[HH*CC];
    __shared__ float sAce[HH*EE];
    __shared__ float sGl[EE];
    __shared__ float sW2[EE];
    __shared__ float sLgP[4][CC];
    __shared__ float sLg[CC];
    __shared__ int   sVcm[CC];
    __shared__ float sMax, sLse;
    __shared__ int   sArg;

    // ---- load cluster embeddings transposed; half owns 25 c's, e = t2 ----
    {
        const float* src = CE + (size_t)b*CC*EE;
        #pragma unroll
        for (int cc = 0; cc < 25; cc++) {
            int c = half*25 + cc;
            sCET[t2*CCP + c] = src[c*EE + t2];
        }
    }

    // ---- combine reduction partials: half 0 -> um, half 1 -> uc ----
    {
        float a = 0.f;
        #pragma unroll
        for (int s = 0; s < SPLIT; s++)
            a += g_part[(b*SPLIT + s)*2*EE + half*EE + t2];
        a *= (1.f/NN);
        if (half == 0) sCtx[t2] = a; else sUC[t2] = a;
    }
    if (half == 0) { sCtx[EE + t2] = cur[b*EE + t2]; sQcd[t2] = g_qcd[b*EE + t2]; }
    else           sCtx[2*EE + t2] = depot[b*EE + t2];
    if (t < CC) sVcm[t] = (vcm_g[b*CC + t] != 0);
    __syncthreads();

    if (t == 0) {                      // vcm[0] = !all(vcm[1:])
        int all = 1;
        for (int c = 1; c < CC; c++) all &= (sVcm[c] != 0);
        sVcm[0] = !all;
    }

    // ---- q = um@W0 + qcd; split-K over halves (64 MACs each, 4 accs) ----
    {
        const int i0 = half*64;
        float a0=0.f,a1=0.f,a2=0.f,a3=0.f;
        #pragma unroll 4
        for (int i = 0; i < 64; i += 4) {
            a0 += sCtx[i0+i  ] * g_Wqf[(i0+i  )*EE + t2];
            a1 += sCtx[i0+i+1] * g_Wqf[(i0+i+1)*EE + t2];
            a2 += sCtx[i0+i+2] * g_Wqf[(i0+i+2)*EE + t2];
            a3 += sCtx[i0+i+3] * g_Wqf[(i0+i+3)*EE + t2];
        }
        sP2[half][t2] = (a0+a1)+(a2+a3);
    }
    __syncthreads();
    if (half == 0) sQ[t2] = sP2[0][t2] + sP2[1][t2] + sQcd[t2];
    __syncthreads();

    // ---- kq[h][e]: 1024 outputs over 256 threads (4 each), 16 MACs ----
    #pragma unroll
    for (int k = 0; k < 4; k++) {
        int idx = t + 256*k;
        int h = idx >> 7, e = idx & 127;
        float a0=0.f,a1=0.f;
        #pragma unroll
        for (int d = 0; d < DD; d += 2) {
            a0 += sQ[h*DD + d  ] * g_WkfT[(h*DD + d  )*EE + e];
            a1 += sQ[h*DD + d+1] * g_WkfT[(h*DD + d+1)*EE + e];
        }
        sKQ[h*EE + e] = a0 + a1;
    }
    __syncthreads();

    // ---- scores: 400 outputs, 128 MACs, 4 accs ----
    for (int idx = t; idx < HH*CC; idx += 256) {
        int h = idx / CC, c = idx % CC;
        float a0=0.f,a1=0.f,a2=0.f,a3=0.f;
        #pragma unroll 4
        for (int e = 0; e < EE; e += 4) {
            a0 += sCET[(e  )*CCP + c] * sKQ[h*EE + e  ];
            a1 += sCET[(e+1)*CCP + c] * sKQ[h*EE + e+1];
            a2 += sCET[(e+2)*CCP + c] * sKQ[h*EE + e+2];
            a3 += sCET[(e+3)*CCP + c] * sKQ[h*EE + e+3];
        }
        float a = ((a0+a1)+(a2+a3)) * 0.25f;   // 1/sqrt(16)
        if (sVcm[c]) a = NEGV;
        sSc[h*CC + c] = a;
    }
    __syncthreads();

    // ---- softmax: warp h owns head h ----
    {
        int h = warp;
        float v0 = sSc[h*CC + lane];
        float v1 = (lane < CC-32) ? sSc[h*CC + lane + 32] : -3e38f;
        float mx = fmaxf(v0, v1);
        #pragma unroll
        for (int o = 16; o > 0; o >>= 1)
            mx = fmaxf(mx, __shfl_xor_sync(0xffffffffu, mx, o));
        float e0 = expf(v0 - mx);
        float e1 = (lane < CC-32) ? expf(v1 - mx) : 0.f;
        float sm = e0 + e1;
        #pragma unroll
        for (int o = 16; o > 0; o >>= 1)
            sm += __shfl_xor_sync(0xffffffffu, sm, o);
        float inv = 1.f / sm;
        sAt[h*CC + lane] = e0 * inv;
        if (lane < CC-32) sAt[h*CC + lane + 32] = e1 * inv;
    }
    __syncthreads();

    // ---- a_ce[h][e]: 1024 outputs over 256 threads, 50 MACs, 2 accs ----
    #pragma unroll
    for (int k = 0; k < 4; k++) {
        int idx = t + 256*k;
        int h = idx >> 7, e = idx & 127;
        float a0=0.f,a1=0.f;
        #pragma unroll 5
        for (int c = 0; c < CC; c += 2) {
            a0 += sAt[h*CC + c  ] * sCET[e*CCP + c  ];
            a1 += sAt[h*CC + c+1] * sCET[e*CCP + c+1];
        }
        sAce[h*EE + e] = a0 + a1;
    }
    __syncthreads();

    // ---- glimpse[j=t2]: 128-MAC split-K over halves (h = j/16) ----
    {
        int h = t2 / DD;
        const int e0 = half*64;
        float a0=0.f,a1=0.f,a2=0.f,a3=0.f;
        #pragma unroll 4
        for (int e = 0; e < 64; e += 4) {
            a0 += sAce[h*EE + e0+e  ] * g_Wvf[(e0+e  )*EE + t2];
            a1 += sAce[h*EE + e0+e+1] * g_Wvf[(e0+e+1)*EE + t2];
            a2 += sAce[h*EE + e0+e+2] * g_Wvf[(e0+e+2)*EE + t2];
            a3 += sAce[h*EE + e0+e+3] * g_Wvf[(e0+e+3)*EE + t2];
        }
        sP2[half][t2] = (a0+a1)+(a2+a3);
    }
    __syncthreads();
    if (half == 0) sGl[t2] = sP2[0][t2] + sP2[1][t2];
    __syncthreads();

    // ---- w2[e=t2] = sum_j gl[j] * WoKs[j][e]: split-K over halves ----
    {
        const int j0 = half*64;
        float a0=0.f,a1=0.f,a2=0.f,a3=0.f;
        #pragma unroll 4
        for (int j = 0; j < 64; j += 4) {
            a0 += sGl[j0+j  ] * g_WoKs[(j0+j  )*EE + t2];
            a1 += sGl[j0+j+1] * g_WoKs[(j0+j+1)*EE + t2];
            a2 += sGl[j0+j+2] * g_WoKs[(j0+j+2)*EE + t2];
            a3 += sGl[j0+j+3] * g_WoKs[(j0+j+3)*EE + t2];
        }
        sP2[half][t2] = (a0+a1)+(a2+a3);
    }
    __syncthreads();
    if (half == 0) sW2[t2] = sP2[0][t2] + sP2[1][t2];
    __syncthreads();

    // ---- logit[c]: 50 outputs, split over 4 quarters of e ----
    {
        int c = t & 63, q4 = t >> 6;
        if (c < CC) {
            const int e0 = q4*32;
            float a0=0.f,a1=0.f;
            #pragma unroll 4
            for (int e = 0; e < 32; e += 2) {
                a0 += sCET[(e0+e  )*CCP + c] * sW2[e0+e  ];
                a1 += sCET[(e0+e+1)*CCP + c] * sW2[e0+e+1];
            }
            sLgP[q4][c] = a0 + a1;
        }
    }
    __syncthreads();
    if (t < CC) {
        float a = (sLgP[0][t] + sLgP[1][t]) + (sLgP[2][t] + sLgP[3][t]);
        a *= 0.08838834764831845f;     // 1/sqrt(128)
        a = tanhf(a) * 10.f;
        if (sVcm[t]) a = NEGV;
        sLg[t] = a;
    }
    __syncthreads();

    // ---- argmax (first-index ties) + logsumexp, warp 0 via shfl ----
    if (warp == 0) {
        float v0 = sLg[lane];
        float v1 = (lane < CC-32) ? sLg[lane + 32] : -3e38f;
        float v = v0; int ix = lane;
        if (v1 > v) { v = v1; ix = lane + 32; }
        #pragma unroll
        for (int o = 16; o > 0; o >>= 1) {
            float ov = __shfl_xor_sync(0xffffffffu, v, o);
            int   oi = __shfl_xor_sync(0xffffffffu, ix, o);
            if (ov > v || (ov == v && oi < ix)) { v = ov; ix = oi; }
        }
        float mx = v;
        float sm = expf(v0 - mx) + ((lane < CC-32) ? expf(v1 - mx) : 0.f);
        #pragma unroll
        for (int o = 16; o > 0; o >>= 1)
            sm += __shfl_xor_sync(0xffffffffu, sm, o);
        if (lane == 0) { sMax = mx; sLse = logf(sm); sArg = ix; }
    }
    __syncthreads();

    const int  guid = sArg;
    const bool isn  = isnew[b] != 0;
    const float ge  = sCET[t2*CCP + guid];

    const size_t OFF1 = (size_t)BB*4*EE;            // guid_embed_out
    const size_t OFF2 = OFF1 + (size_t)BB*EE;       // guid_out
    const size_t OFF3 = OFF2 + BB;                  // clu_prob

    float* ao = out + (size_t)b*4*EE;
    const float* ac = augc + (size_t)b*4*EE;
    if (half == 0) {
        ao[t2]        = isn ? sUC[t2]          : ac[t2];
        ao[2*EE + t2] = isn ? ge               : ac[2*EE + t2];
        out[OFF1 + (size_t)b*EE + t2] = isn ? ge : gein[b*EE + t2];
    } else {
        ao[EE + t2]   = isn ? sCtx[EE + t2]    : ac[EE + t2];
        ao[3*EE + t2] = isn ? sCtx[2*EE + t2]  : ac[3*EE + t2];
    }
    if (t == 0) out[OFF2 + b] = (float)(isn ? guid : guid_in[b]);
    if (t < CC) out[OFF3 + (size_t)b*CC + t] = isn ? (sLg[t] - sMax - sLse) : 0.f;
}

// ---------------------------------------------------------------------------
extern "C" void kernel_launch(void* const* d_in, const int* in_sizes, int n_in,
                              void* d_out, int out_size) {
    const float* depot = (const float*)d_in[0];
    const float* CE    = (const float*)d_in[1];
    const float* cur   = (const float*)d_in[2];
    const float* nodes = (const float*)d_in[3];
    const float* augc  = (const float*)d_in[4];
    const float* gein  = (const float*)d_in[5];
    const float* Wq    = (const float*)d_in[6];
    const float* Wk    = (const float*)d_in[7];
    const float* Wv    = (const float*)d_in[8];
    const float* Wks   = (const float*)d_in[9];
    const float* mWq   = (const float*)d_in[10];
    const float* mWk   = (const float*)d_in[11];
    const float* mWv   = (const float*)d_in[12];
    const float* Wo    = (const float*)d_in[13];
    const int* isnew   = (const int*)d_in[14];   // bool -> int32
    const int* mask    = (const int*)d_in[15];   // bool -> int32
    const int* cmask   = (const int*)d_in[16];   // bool -> int32
    const int* vcm     = (const int*)d_in[17];   // bool -> int32
    const int* guid    = (const int*)d_in[18];
    // d_in[19] = step (unused)

    dim3 gr(BB, SPLIT + 2);   // y=0,1 prep (896 rows) ; y=2..9 reduce
    k_pre<<<gr, 128>>>(nodes, mask, cmask, Wq, Wk, Wv, Wks, Wo,
                       mWq, mWk, mWv, cur, depot);
    k_main<<<BB, 256>>>(depot, CE, cur, augc, gein, isnew, vcm, guid,
                        (float*)d_out);
}

// round 16
// speedup vs baseline: 1.1911x; 1.0589x over previous
#include <cuda_runtime.h>
#include <cstdint>
#include <cmath>

#define BB 512
#define NN 1000
#define CC 50
#define CCP 51              // pitch for transposed cluster tile (odd -> conflict-free)
#define EE 128
#define HH 8
#define DD 16
#define SPLIT 8
#define NPS (NN/SPLIT)
#define NEGV (-1e9f)
#define FUSE_ROWS (6*EE)    // 768 zero-smem prep rows in k_pre

// scratch (no cudaMalloc allowed)
__device__ float g_part[BB*SPLIT*2*EE];   // [b][split][{mask, mask|cmask}][e]
__device__ float g_Wqf [3*EE*EE];         // Wq @ mha_Wq   (384 x 128), [i][j]
__device__ float g_WkfT[EE*EE];           // (Wk @ mha_Wk)^T : [j][e]
__device__ float g_Wvf [EE*EE];           // Wv @ mha_Wv    : [e][j]
__device__ float g_WksT[EE*EE];           // Wks^T          : [f][e]
__device__ float g_WoKs[EE*EE];           // Wo @ Wks^T     : [j][e]
__device__ float g_qcd [BB*EE];           // ([0|cur|depot] @ Wqf) per batch

// ---------------------------------------------------------------------------
// Kernel 1: R8-EXACT. Masked reduction (simple predicated loop) + zero-smem
// prep planes. grid (BB, SPLIT+2), 128 threads. Measured 33.1us.
// ---------------------------------------------------------------------------
__global__ void __launch_bounds__(128) k_pre(
    const float* __restrict__ nodes,
    const int* __restrict__ mask, const int* __restrict__ cmask,
    const float* __restrict__ Wq, const float* __restrict__ Wk,
    const float* __restrict__ Wv, const float* __restrict__ Wks,
    const float* __restrict__ mWq, const float* __restrict__ mWk,
    const float* __restrict__ mWv)
{
    const int b = blockIdx.x, y = blockIdx.y, t = threadIdx.x;

    if (y >= SPLIT) {
        int fr = (y - SPLIT)*BB + b;
        if (fr >= FUSE_ROWS) return;
        if (fr < 3*EE) {
            const float* a_ = Wq + fr*EE;
            float s0=0.f,s1=0.f,s2=0.f,s3=0.f;
            #pragma unroll 8
            for (int e = 0; e < EE; e += 4) {
                s0 += a_[e  ] * mWq[(e  )*EE + t];
                s1 += a_[e+1] * mWq[(e+1)*EE + t];
                s2 += a_[e+2] * mWq[(e+2)*EE + t];
                s3 += a_[e+3] * mWq[(e+3)*EE + t];
            }
            g_Wqf[fr*EE + t] = (s0+s1)+(s2+s3);
        } else if (fr < 4*EE) {
            const int e0 = fr - 3*EE;
            const float* a_ = Wk + e0*EE;
            float s0=0.f,s1=0.f,s2=0.f,s3=0.f;
            #pragma unroll 8
            for (int x = 0; x < EE; x += 4) {
                s0 += a_[x  ] * mWk[(x  )*EE + t];
                s1 += a_[x+1] * mWk[(x+1)*EE + t];
                s2 += a_[x+2] * mWk[(x+2)*EE + t];
                s3 += a_[x+3] * mWk[(x+3)*EE + t];
            }
            g_WkfT[t*EE + e0] = (s0+s1)+(s2+s3);   // transposed
        } else if (fr < 5*EE) {
            const int e0 = fr - 4*EE;
            const float* a_ = Wv + e0*EE;
            float s0=0.f,s1=0.f,s2=0.f,s3=0.f;
            #pragma unroll 8
            for (int x = 0; x < EE; x += 4) {
                s0 += a_[x  ] * mWv[(x  )*EE + t];
                s1 += a_[x+1] * mWv[(x+1)*EE + t];
                s2 += a_[x+2] * mWv[(x+2)*EE + t];
                s3 += a_[x+3] * mWv[(x+3)*EE + t];
            }
            g_Wvf[e0*EE + t] = (s0+s1)+(s2+s3);
        } else {
            const int f = fr - 5*EE;
            g_WksT[f*EE + t] = Wks[t*EE + f];      // transpose copy
        }
        return;
    }

    __shared__ uint8_t sM[NPS], sC[NPS];
    __shared__ float4  sR0[4][32], sR1[4][32];

    const int* m  = mask  + b*NN + y*NPS;
    const int* cm = cmask + b*NN + y*NPS;
    if (t < NPS) {
        sM[t] = (uint8_t)(m[t]  != 0);
        sC[t] = (uint8_t)(cm[t] != 0);
    }
    __syncthreads();

    const int warp = t >> 5, lane = t & 31;
    const float4* base = (const float4*)(nodes + ((size_t)b*NN + (size_t)y*NPS)*EE);

    float4 a0 = make_float4(0.f,0.f,0.f,0.f);
    float4 a1 = make_float4(0.f,0.f,0.f,0.f);
    for (int r = warp; r < NPS; r += 4) {
        if (!sM[r]) {                        // warp-uniform: skip masked rows
            float4 v = __ldg(base + r*32 + lane);
            a0.x += v.x; a0.y += v.y; a0.z += v.z; a0.w += v.w;
            if (!sC[r]) { a1.x += v.x; a1.y += v.y; a1.z += v.z; a1.w += v.w; }
        }
    }
    sR0[warp][lane] = a0;
    sR1[warp][lane] = a1;
    __syncthreads();

    const float* p0 = (const float*)sR0;
    const float* p1 = (const float*)sR1;
    float s0 = p0[t] + p0[128 + t] + p0[256 + t] + p0[384 + t];
    float s1 = p1[t] + p1[128 + t] + p1[256 + t] + p1[384 + t];
    int idx = (b*SPLIT + y)*2*EE + t;
    g_part[idx]      = s0;
    g_part[idx + EE] = s1;
}

// ---------------------------------------------------------------------------
// Kernel 1.5 (tiny): WoKs from WksT (coalesced) and qcd from g_Wqf — both
// race-free now that k_pre finished. 192 blocks, ~4-6us.
// ---------------------------------------------------------------------------
__global__ void __launch_bounds__(128) k_mid(
    const float* __restrict__ Wo,
    const float* __restrict__ cur, const float* __restrict__ depot)
{
    const int r = blockIdx.x, t = threadIdx.x;
    if (r < EE) {
        // WoKs[j=r][e=t] = sum_f Wo[r][f] * WksT[f][e]   (all coalesced)
        const float* wo = Wo + r*EE;
        float s0=0.f,s1=0.f,s2=0.f,s3=0.f;
        #pragma unroll 8
        for (int f = 0; f < EE; f += 4) {
            s0 += wo[f  ] * g_WksT[(f  )*EE + t];
            s1 += wo[f+1] * g_WksT[(f+1)*EE + t];
            s2 += wo[f+2] * g_WksT[(f+2)*EE + t];
            s3 += wo[f+3] * g_WksT[(f+3)*EE + t];
        }
        g_WoKs[r*EE + t] = (s0+s1)+(s2+s3);
    } else {
        // qcd for 8 batches: qcd[b][j=t] = sum_{i=0..255} cd[i]*Wqf[128+i][j]
        const int g8 = (r - EE)*8;
        __shared__ float sCD[8][2*EE];
        #pragma unroll
        for (int nb = 0; nb < 8; nb++) {
            sCD[nb][t]      = cur  [(g8 + nb)*EE + t];
            sCD[nb][EE + t] = depot[(g8 + nb)*EE + t];
        }
        __syncthreads();
        float acc[8] = {0.f,0.f,0.f,0.f,0.f,0.f,0.f,0.f};
        #pragma unroll 4
        for (int i = 0; i < 2*EE; i += 4) {
            float w0 = g_Wqf[(EE + i  )*EE + t];
            float w1 = g_Wqf[(EE + i+1)*EE + t];
            float w2 = g_Wqf[(EE + i+2)*EE + t];
            float w3 = g_Wqf[(EE + i+3)*EE + t];
            #pragma unroll
            for (int nb = 0; nb < 8; nb++)
                acc[nb] += sCD[nb][i]*w0 + sCD[nb][i+1]*w1
                         + sCD[nb][i+2]*w2 + sCD[nb][i+3]*w3;
        }
        #pragma unroll
        for (int nb = 0; nb < 8; nb++)
            g_qcd[(g8 + nb)*EE + t] = acc[nb];
    }
}

// ---------------------------------------------------------------------------
// Kernel 2: math chain per batch, 256 threads. R13 structure + register
// prefetch: weight loads are data-independent, so issue them EARLY and let
// the L2 latency drain under unrelated work.
// ---------------------------------------------------------------------------
__global__ void __launch_bounds__(256) k_main(
    const float* __restrict__ depot, const float* __restrict__ CE,
    const float* __restrict__ cur,   const float* __restrict__ augc,
    const float* __restrict__ gein,
    const int* __restrict__ isnew, const int* __restrict__ vcm_g,
    const int* __restrict__ guid_in, float* __restrict__ out)
{
    const int b = blockIdx.x, t = threadIdx.x;
    const int t2 = t & 127, half = t >> 7;
    const int warp = t >> 5, lane = t & 31;

    __shared__ float sCET[EE*CCP];
    __shared__ float sCtx[3*EE];
    __shared__ float sUC[EE];
    __shared__ float sQcd[EE];
    __shared__ float sP2[2][EE];
    __shared__ float sQ[EE];
    __shared__ float sKQ[HH*EE];
    __shared__ float sSc[HH*CC];
    __shared__ float sAt[HH*CC];
    __shared__ float sAce[HH*EE];
    __shared__ float sGl[EE];
    __shared__ float sW2[EE];
    __shared__ float sLgP[4][CC];
    __shared__ float sLg[CC];
    __shared__ int   sVcm[CC];
    __shared__ float sMax, sLse;
    __shared__ int   sArg;

    // ---- PREFETCH wave 1: q weights + kq weights (128 regs), issued first
    float wq[64], wkq[64];
    {
        const int i0 = half*64;
        #pragma unroll
        for (int i = 0; i < 64; i++) wq[i] = g_Wqf[(i0+i)*EE + t2];
        #pragma unroll
        for (int k = 0; k < 4; k++) {
            int idx = t + 256*k;
            int h = idx >> 7, e = idx & 127;
            #pragma unroll
            for (int d = 0; d < DD; d++)
                wkq[k*DD + d] = g_WkfT[(h*DD + d)*EE + e];
        }
    }

    // ---- cluster tile (transposed) while prefetch drains ----
    {
        const float* src = CE + (size_t)b*CC*EE;
        #pragma unroll
        for (int cc = 0; cc < 25; cc++) {
            int c = half*25 + cc;
            sCET[t2*CCP + c] = src[c*EE + t2];
        }
    }

    // ---- combine reduction partials: half 0 -> um, half 1 -> uc ----
    {
        float a = 0.f;
        #pragma unroll
        for (int s = 0; s < SPLIT; s++)
            a += g_part[(b*SPLIT + s)*2*EE + half*EE + t2];
        a *= (1.f/NN);
        if (half == 0) sCtx[t2] = a; else sUC[t2] = a;
    }
    if (half == 0) { sCtx[EE + t2] = cur[b*EE + t2]; sQcd[t2] = g_qcd[b*EE + t2]; }
    else           sCtx[2*EE + t2] = depot[b*EE + t2];
    if (t < CC) sVcm[t] = (vcm_g[b*CC + t] != 0);
    __syncthreads();

    if (t == 0) {                      // vcm[0] = !all(vcm[1:])
        int all = 1;
        for (int c = 1; c < CC; c++) all &= (sVcm[c] != 0);
        sVcm[0] = !all;
    }

    // ---- q = um@W0 + qcd (weights in registers) ----
    {
        const int i0 = half*64;
        float a0=0.f,a1=0.f,a2=0.f,a3=0.f;
        #pragma unroll
        for (int i = 0; i < 64; i += 4) {
            a0 += sCtx[i0+i  ] * wq[i  ];
            a1 += sCtx[i0+i+1] * wq[i+1];
            a2 += sCtx[i0+i+2] * wq[i+2];
            a3 += sCtx[i0+i+3] * wq[i+3];
        }
        sP2[half][t2] = (a0+a1)+(a2+a3);
    }
    __syncthreads();
    if (half == 0) sQ[t2] = sP2[0][t2] + sP2[1][t2] + sQcd[t2];
    __syncthreads();

    // ---- kq[h][e] (weights in registers) ----
    #pragma unroll
    for (int k = 0; k < 4; k++) {
        int idx = t + 256*k;
        int h = idx >> 7, e = idx & 127;
        float a0=0.f,a1=0.f;
        #pragma unroll
        for (int d = 0; d < DD; d += 2) {
            a0 += sQ[h*DD + d  ] * wkq[k*DD + d  ];
            a1 += sQ[h*DD + d+1] * wkq[k*DD + d+1];
        }
        sKQ[h*EE + e] = a0 + a1;
    }
    __syncthreads();

    // ---- PREFETCH wave 2: glimpse + WoKs weights (128 regs); latency
    // drains under scores + softmax + a_ce (the long LDS stretch).
    float wv[64], wo[64];
    {
        const int e0 = half*64;
        #pragma unroll
        for (int e = 0; e < 64; e++) wv[e] = g_Wvf[(e0+e)*EE + t2];
        #pragma unroll
        for (int j = 0; j < 64; j++) wo[j] = g_WoKs[(e0+j)*EE + t2];
    }

    // ---- scores: 400 outputs, 128 MACs, 4 accs ----
    for (int idx = t; idx < HH*CC; idx += 256) {
        int h = idx / CC, c = idx % CC;
        float a0=0.f,a1=0.f,a2=0.f,a3=0.f;
        #pragma unroll 4
        for (int e = 0; e < EE; e += 4) {
            a0 += sCET[(e  )*CCP + c] * sKQ[h*EE + e  ];
            a1 += sCET[(e+1)*CCP + c] * sKQ[h*EE + e+1];
            a2 += sCET[(e+2)*CCP + c] * sKQ[h*EE + e+2];
            a3 += sCET[(e+3)*CCP + c] * sKQ[h*EE + e+3];
        }
        float a = ((a0+a1)+(a2+a3)) * 0.25f;   // 1/sqrt(16)
        if (sVcm[c]) a = NEGV;
        sSc[h*CC + c] = a;
    }
    __syncthreads();

    // ---- softmax: warp h owns head h ----
    {
        int h = warp;
        float v0 = sSc[h*CC + lane];
        float v1 = (lane < CC-32) ? sSc[h*CC + lane + 32] : -3e38f;
        float mx = fmaxf(v0, v1);
        #pragma unroll
        for (int o = 16; o > 0; o >>= 1)
            mx = fmaxf(mx, __shfl_xor_sync(0xffffffffu, mx, o));
        float e0 = expf(v0 - mx);
        float e1 = (lane < CC-32) ? expf(v1 - mx) : 0.f;
        float sm = e0 + e1;
        #pragma unroll
        for (int o = 16; o > 0; o >>= 1)
            sm += __shfl_xor_sync(0xffffffffu, sm, o);
        float inv = 1.f / sm;
        sAt[h*CC + lane] = e0 * inv;
        if (lane < CC-32) sAt[h*CC + lane + 32] = e1 * inv;
    }
    __syncthreads();

    // ---- a_ce[h][e]: 1024 outputs over 256 threads, 50 MACs ----
    #pragma unroll
    for (int k = 0; k < 4; k++) {
        int idx = t + 256*k;
        int h = idx >> 7, e = idx & 127;
        float a0=0.f,a1=0.f;
        #pragma unroll 5
        for (int c = 0; c < CC; c += 2) {
            a0 += sAt[h*CC + c  ] * sCET[e*CCP + c  ];
            a1 += sAt[h*CC + c+1] * sCET[e*CCP + c+1];
        }
        sAce[h*EE + e] = a0 + a1;
    }
    __syncthreads();

    // ---- glimpse[j=t2]: split-K over halves, weights in registers ----
    {
        int h = t2 / DD;
        const int e0 = half*64;
        float a0=0.f,a1=0.f,a2=0.f,a3=0.f;
        #pragma unroll
        for (int e = 0; e < 64; e += 4) {
            a0 += sAce[h*EE + e0+e  ] * wv[e  ];
            a1 += sAce[h*EE + e0+e+1] * wv[e+1];
            a2 += sAce[h*EE + e0+e+2] * wv[e+2];
            a3 += sAce[h*EE + e0+e+3] * wv[e+3];
        }
        sP2[half][t2] = (a0+a1)+(a2+a3);
    }
    __syncthreads();
    if (half == 0) sGl[t2] = sP2[0][t2] + sP2[1][t2];
    __syncthreads();

    // ---- w2[e=t2] = sum_j gl[j]*WoKs[j][e], weights in registers ----
    {
        const int j0 = half*64;
        float a0=0.f,a1=0.f,a2=0.f,a3=0.f;
        #pragma unroll
        for (int j = 0; j < 64; j += 4) {
            a0 += sGl[j0+j  ] * wo[j  ];
            a1 += sGl[j0+j+1] * wo[j+1];
            a2 += sGl[j0+j+2] * wo[j+2];
            a3 += sGl[j0+j+3] * wo[j+3];
        }
        sP2[half][t2] = (a0+a1)+(a2+a3);
    }
    __syncthreads();
    if (half == 0) sW2[t2] = sP2[0][t2] + sP2[1][t2];
    __syncthreads();

    // ---- logit[c]: 50 outputs, split over 4 quarters of e ----
    {
        int c = t & 63, q4 = t >> 6;
        if (c < CC) {
            const int e0 = q4*32;
            float a0=0.f,a1=0.f;
            #pragma unroll 4
            for (int e = 0; e < 32; e += 2) {
                a0 += sCET[(e0+e  )*CCP + c] * sW2[e0+e  ];
                a1 += sCET[(e0+e+1)*CCP + c] * sW2[e0+e+1];
            }
            sLgP[q4][c] = a0 + a1;
        }
    }
    __syncthreads();
    if (t < CC) {
        float a = (sLgP[0][t] + sLgP[1][t]) + (sLgP[2][t] + sLgP[3][t]);
        a *= 0.08838834764831845f;     // 1/sqrt(128)
        a = tanhf(a) * 10.f;
        if (sVcm[t]) a = NEGV;
        sLg[t] = a;
    }
    __syncthreads();

    // ---- argmax (first-index ties) + logsumexp, warp 0 via shfl ----
    if (warp == 0) {
        float v0 = sLg[lane];
        float v1 = (lane < CC-32) ? sLg[lane + 32] : -3e38f;
        float v = v0; int ix = lane;
        if (v1 > v) { v = v1; ix = lane + 32; }
        #pragma unroll
        for (int o = 16; o > 0; o >>= 1) {
            float ov = __shfl_xor_sync(0xffffffffu, v, o);
            int   oi = __shfl_xor_sync(0xffffffffu, ix, o);
            if (ov > v || (ov == v && oi < ix)) { v = ov; ix = oi; }
        }
        float mx = v;
        float sm = expf(v0 - mx) + ((lane < CC-32) ? expf(v1 - mx) : 0.f);
        #pragma unroll
        for (int o = 16; o > 0; o >>= 1)
            sm += __shfl_xor_sync(0xffffffffu, sm, o);
        if (lane == 0) { sMax = mx; sLse = logf(sm); sArg = ix; }
    }
    __syncthreads();

    const int  guid = sArg;
    const bool isn  = isnew[b] != 0;
    const float ge  = sCET[t2*CCP + guid];

    const size_t OFF1 = (size_t)BB*4*EE;            // guid_embed_out
    const size_t OFF2 = OFF1 + (size_t)BB*EE;       // guid_out
    const size_t OFF3 = OFF2 + BB;                  // clu_prob

    float* ao = out + (size_t)b*4*EE;
    const float* ac = augc + (size_t)b*4*EE;
    if (half == 0) {
        ao[t2]        = isn ? sUC[t2]          : ac[t2];
        ao[2*EE + t2] = isn ? ge               : ac[2*EE + t2];
        out[OFF1 + (size_t)b*EE + t2] = isn ? ge : gein[b*EE + t2];
    } else {
        ao[EE + t2]   = isn ? sCtx[EE + t2]    : ac[EE + t2];
        ao[3*EE + t2] = isn ? sCtx[2*EE + t2]  : ac[3*EE + t2];
    }
    if (t == 0) out[OFF2 + b] = (float)(isn ? guid : guid_in[b]);
    if (t < CC) out[OFF3 + (size_t)b*CC + t] = isn ? (sLg[t] - sMax - sLse) : 0.f;
}

// ---------------------------------------------------------------------------
extern "C" void kernel_launch(void* const* d_in, const int* in_sizes, int n_in,
                              void* d_out, int out_size) {
    const float* depot = (const float*)d_in[0];
    const float* CE    = (const float*)d_in[1];
    const float* cur   = (const float*)d_in[2];
    const float* nodes = (const float*)d_in[3];
    const float* augc  = (const float*)d_in[4];
    const float* gein  = (const float*)d_in[5];
    const float* Wq    = (const float*)d_in[6];
    const float* Wk    = (const float*)d_in[7];
    const float* Wv    = (const float*)d_in[8];
    const float* Wks   = (const float*)d_in[9];
    const float* mWq   = (const float*)d_in[10];
    const float* mWk   = (const float*)d_in[11];
    const float* mWv   = (const float*)d_in[12];
    const float* Wo    = (const float*)d_in[13];
    const int* isnew   = (const int*)d_in[14];   // bool -> int32
    const int* mask    = (const int*)d_in[15];   // bool -> int32
    const int* cmask   = (const int*)d_in[16];   // bool -> int32
    const int* vcm     = (const int*)d_in[17];   // bool -> int32
    const int* guid    = (const int*)d_in[18];
    // d_in[19] = step (unused)

    dim3 gr(BB, SPLIT + 2);   // 8 reduce planes + 2 zero-smem prep planes
    k_pre<<<gr, 128>>>(nodes, mask, cmask, Wq, Wk, Wv, Wks, mWq, mWk, mWv);
    k_mid<<<EE + BB/8, 128>>>(Wo, cur, depot);   // 128 WoKs + 64 qcd blocks
    k_main<<<BB, 256>>>(depot, CE, cur, augc, gein, isnew, vcm, guid,
                        (float*)d_out);
}

// round 17
// speedup vs baseline: 1.2921x; 1.0848x over previous
#include <cuda_runtime.h>
#include <cstdint>
#include <cmath>

#define BB 512
#define NN 1000
#define CC 50
#define CCP 51              // pitch for transposed cluster tile (odd -> conflict-free)
#define EE 128
#define HH 8
#define DD 16
#define SPLIT 8
#define NPS (NN/SPLIT)
#define NEGV (-1e9f)
#define FUSE_ROWS (6*EE)    // 768 zero-smem prep rows in k_pre

// scratch (no cudaMalloc allowed)
__device__ float g_part[BB*SPLIT*2*EE];   // [b][split][{mask, mask|cmask}][e]
__device__ float g_Wqf [3*EE*EE];         // Wq @ mha_Wq   (384 x 128), [i][j]
__device__ float g_WkfT[EE*EE];           // (Wk @ mha_Wk)^T : [j][e]
__device__ float g_Wvf [EE*EE];           // Wv @ mha_Wv    : [e][j]
__device__ float g_WksT[EE*EE];           // Wks^T          : [f][e]
__device__ float g_WoKs[EE*EE];           // Wo @ Wks^T     : [j][e]
__device__ float g_qcd [BB*EE];           // (cur@W1 + depot@W2)@mWq per batch

// ---------------------------------------------------------------------------
// Kernel 1: R8-EXACT. Masked reduction (simple predicated loop) + zero-smem
// prep planes. grid (BB, SPLIT+2), 128 threads. Measured 32.3us.
// ---------------------------------------------------------------------------
__global__ void __launch_bounds__(128) k_pre(
    const float* __restrict__ nodes,
    const int* __restrict__ mask, const int* __restrict__ cmask,
    const float* __restrict__ Wq, const float* __restrict__ Wk,
    const float* __restrict__ Wv, const float* __restrict__ Wks,
    const float* __restrict__ mWq, const float* __restrict__ mWk,
    const float* __restrict__ mWv)
{
    const int b = blockIdx.x, y = blockIdx.y, t = threadIdx.x;

    if (y >= SPLIT) {
        int fr = (y - SPLIT)*BB + b;
        if (fr >= FUSE_ROWS) return;
        if (fr < 3*EE) {
            const float* a_ = Wq + fr*EE;
            float s0=0.f,s1=0.f,s2=0.f,s3=0.f;
            #pragma unroll 8
            for (int e = 0; e < EE; e += 4) {
                s0 += a_[e  ] * mWq[(e  )*EE + t];
                s1 += a_[e+1] * mWq[(e+1)*EE + t];
                s2 += a_[e+2] * mWq[(e+2)*EE + t];
                s3 += a_[e+3] * mWq[(e+3)*EE + t];
            }
            g_Wqf[fr*EE + t] = (s0+s1)+(s2+s3);
        } else if (fr < 4*EE) {
            const int e0 = fr - 3*EE;
            const float* a_ = Wk + e0*EE;
            float s0=0.f,s1=0.f,s2=0.f,s3=0.f;
            #pragma unroll 8
            for (int x = 0; x < EE; x += 4) {
                s0 += a_[x  ] * mWk[(x  )*EE + t];
                s1 += a_[x+1] * mWk[(x+1)*EE + t];
                s2 += a_[x+2] * mWk[(x+2)*EE + t];
                s3 += a_[x+3] * mWk[(x+3)*EE + t];
            }
            g_WkfT[t*EE + e0] = (s0+s1)+(s2+s3);   // transposed
        } else if (fr < 5*EE) {
            const int e0 = fr - 4*EE;
            const float* a_ = Wv + e0*EE;
            float s0=0.f,s1=0.f,s2=0.f,s3=0.f;
            #pragma unroll 8
            for (int x = 0; x < EE; x += 4) {
                s0 += a_[x  ] * mWv[(x  )*EE + t];
                s1 += a_[x+1] * mWv[(x+1)*EE + t];
                s2 += a_[x+2] * mWv[(x+2)*EE + t];
                s3 += a_[x+3] * mWv[(x+3)*EE + t];
            }
            g_Wvf[e0*EE + t] = (s0+s1)+(s2+s3);
        } else {
            const int f = fr - 5*EE;
            g_WksT[f*EE + t] = Wks[t*EE + f];      // transpose copy
        }
        return;
    }

    __shared__ uint8_t sM[NPS], sC[NPS];
    __shared__ float4  sR0[4][32], sR1[4][32];

    const int* m  = mask  + b*NN + y*NPS;
    const int* cm = cmask + b*NN + y*NPS;
    if (t < NPS) {
        sM[t] = (uint8_t)(m[t]  != 0);
        sC[t] = (uint8_t)(cm[t] != 0);
    }
    __syncthreads();

    const int warp = t >> 5, lane = t & 31;
    const float4* base = (const float4*)(nodes + ((size_t)b*NN + (size_t)y*NPS)*EE);

    float4 a0 = make_float4(0.f,0.f,0.f,0.f);
    float4 a1 = make_float4(0.f,0.f,0.f,0.f);
    for (int r = warp; r < NPS; r += 4) {
        if (!sM[r]) {                        // warp-uniform: skip masked rows
            float4 v = __ldg(base + r*32 + lane);
            a0.x += v.x; a0.y += v.y; a0.z += v.z; a0.w += v.w;
            if (!sC[r]) { a1.x += v.x; a1.y += v.y; a1.z += v.z; a1.w += v.w; }
        }
    }
    sR0[warp][lane] = a0;
    sR1[warp][lane] = a1;
    __syncthreads();

    const float* p0 = (const float*)sR0;
    const float* p1 = (const float*)sR1;
    float s0 = p0[t] + p0[128 + t] + p0[256 + t] + p0[384 + t];
    float s1 = p1[t] + p1[128 + t] + p1[256 + t] + p1[384 + t];
    int idx = (b*SPLIT + y)*2*EE + t;
    g_part[idx]      = s0;
    g_part[idx + EE] = s1;
}

// ---------------------------------------------------------------------------
// Kernel 1.5 (tiny): WoKs from WksT (coalesced) and qcd from g_Wqf — both
// race-free after k_pre. 192 blocks, ~4-5us.
// ---------------------------------------------------------------------------
__global__ void __launch_bounds__(128) k_mid(
    const float* __restrict__ Wo,
    const float* __restrict__ cur, const float* __restrict__ depot)
{
    const int r = blockIdx.x, t = threadIdx.x;
    if (r < EE) {
        // WoKs[j=r][e=t] = sum_f Wo[r][f] * WksT[f][e]   (all coalesced)
        const float* wo = Wo + r*EE;
        float s0=0.f,s1=0.f,s2=0.f,s3=0.f;
        #pragma unroll 8
        for (int f = 0; f < EE; f += 4) {
            s0 += wo[f  ] * g_WksT[(f  )*EE + t];
            s1 += wo[f+1] * g_WksT[(f+1)*EE + t];
            s2 += wo[f+2] * g_WksT[(f+2)*EE + t];
            s3 += wo[f+3] * g_WksT[(f+3)*EE + t];
        }
        g_WoKs[r*EE + t] = (s0+s1)+(s2+s3);
    } else {
        // qcd for 8 batches: qcd[b][j=t] = sum_{i=0..255} cd[i]*Wqf[128+i][j]
        const int g8 = (r - EE)*8;
        __shared__ float sCD[8][2*EE];
        #pragma unroll
        for (int nb = 0; nb < 8; nb++) {
            sCD[nb][t]      = cur  [(g8 + nb)*EE + t];
            sCD[nb][EE + t] = depot[(g8 + nb)*EE + t];
        }
        __syncthreads();
        float acc[8] = {0.f,0.f,0.f,0.f,0.f,0.f,0.f,0.f};
        #pragma unroll 4
        for (int i = 0; i < 2*EE; i += 4) {
            float w0 = g_Wqf[(EE + i  )*EE + t];
            float w1 = g_Wqf[(EE + i+1)*EE + t];
            float w2 = g_Wqf[(EE + i+2)*EE + t];
            float w3 = g_Wqf[(EE + i+3)*EE + t];
            #pragma unroll
            for (int nb = 0; nb < 8; nb++)
                acc[nb] += sCD[nb][i]*w0 + sCD[nb][i+1]*w1
                         + sCD[nb][i+2]*w2 + sCD[nb][i+3]*w3;
        }
        #pragma unroll
        for (int nb = 0; nb < 8; nb++)
            g_qcd[(g8 + nb)*EE + t] = acc[nb];
    }
}

// ---------------------------------------------------------------------------
// Kernel 2: math chain per batch, 256 threads. EXACT R13 body (measured
// 33.5us three times; 54 regs, no spill).
// ---------------------------------------------------------------------------
__global__ void __launch_bounds__(256) k_main(
    const float* __restrict__ depot, const float* __restrict__ CE,
    const float* __restrict__ cur,   const float* __restrict__ augc,
    const float* __restrict__ gein,
    const int* __restrict__ isnew, const int* __restrict__ vcm_g,
    const int* __restrict__ guid_in, float* __restrict__ out)
{
    const int b = blockIdx.x, t = threadIdx.x;
    const int t2 = t & 127, half = t >> 7;
    const int warp = t >> 5, lane = t & 31;

    __shared__ float sCET[EE*CCP];
    __shared__ float sCtx[3*EE];
    __shared__ float sUC[EE];
    __shared__ float sQcd[EE];
    __shared__ float sP2[2][EE];
    __shared__ float sQ[EE];
    __shared__ float sKQ[HH*EE];
    __shared__ float sSc[HH*CC];
    __shared__ float sAt[HH*CC];
    __shared__ float sAce[HH*EE];
    __shared__ float sGl[EE];
    __shared__ float sW2[EE];
    __shared__ float sLgP[4][CC];
    __shared__ float sLg[CC];
    __shared__ int   sVcm[CC];
    __shared__ float sMax, sLse;
    __shared__ int   sArg;

    // ---- load cluster embeddings transposed; half owns 25 c's, e = t2 ----
    {
        const float* src = CE + (size_t)b*CC*EE;
        #pragma unroll
        for (int cc = 0; cc < 25; cc++) {
            int c = half*25 + cc;
            sCET[t2*CCP + c] = src[c*EE + t2];
        }
    }

    // ---- combine reduction partials: half 0 -> um, half 1 -> uc ----
    {
        float a = 0.f;
        #pragma unroll
        for (int s = 0; s < SPLIT; s++)
            a += g_part[(b*SPLIT + s)*2*EE + half*EE + t2];
        a *= (1.f/NN);
        if (half == 0) sCtx[t2] = a; else sUC[t2] = a;
    }
    if (half == 0) { sCtx[EE + t2] = cur[b*EE + t2]; sQcd[t2] = g_qcd[b*EE + t2]; }
    else           sCtx[2*EE + t2] = depot[b*EE + t2];
    if (t < CC) sVcm[t] = (vcm_g[b*CC + t] != 0);
    __syncthreads();

    if (t == 0) {                      // vcm[0] = !all(vcm[1:])
        int all = 1;
        for (int c = 1; c < CC; c++) all &= (sVcm[c] != 0);
        sVcm[0] = !all;
    }

    // ---- q = um@W0 + qcd; split-K over halves (64 MACs each, 4 accs) ----
    {
        const int i0 = half*64;
        float a0=0.f,a1=0.f,a2=0.f,a3=0.f;
        #pragma unroll 4
        for (int i = 0; i < 64; i += 4) {
            a0 += sCtx[i0+i  ] * g_Wqf[(i0+i  )*EE + t2];
            a1 += sCtx[i0+i+1] * g_Wqf[(i0+i+1)*EE + t2];
            a2 += sCtx[i0+i+2] * g_Wqf[(i0+i+2)*EE + t2];
            a3 += sCtx[i0+i+3] * g_Wqf[(i0+i+3)*EE + t2];
        }
        sP2[half][t2] = (a0+a1)+(a2+a3);
    }
    __syncthreads();
    if (half == 0) sQ[t2] = sP2[0][t2] + sP2[1][t2] + sQcd[t2];
    __syncthreads();

    // ---- kq[h][e]: 1024 outputs over 256 threads (4 each), 16 MACs ----
    #pragma unroll
    for (int k = 0; k < 4; k++) {
        int idx = t + 256*k;
        int h = idx >> 7, e = idx & 127;
        float a0=0.f,a1=0.f;
        #pragma unroll
        for (int d = 0; d < DD; d += 2) {
            a0 += sQ[h*DD + d  ] * g_WkfT[(h*DD + d  )*EE + e];
            a1 += sQ[h*DD + d+1] * g_WkfT[(h*DD + d+1)*EE + e];
        }
        sKQ[h*EE + e] = a0 + a1;
    }
    __syncthreads();

    // ---- scores: 400 outputs, 128 MACs, 4 accs ----
    for (int idx = t; idx < HH*CC; idx += 256) {
        int h = idx / CC, c = idx % CC;
        float a0=0.f,a1=0.f,a2=0.f,a3=0.f;
        #pragma unroll 4
        for (int e = 0; e < EE; e += 4) {
            a0 += sCET[(e  )*CCP + c] * sKQ[h*EE + e  ];
            a1 += sCET[(e+1)*CCP + c] * sKQ[h*EE + e+1];
            a2 += sCET[(e+2)*CCP + c] * sKQ[h*EE + e+2];
            a3 += sCET[(e+3)*CCP + c] * sKQ[h*EE + e+3];
        }
        float a = ((a0+a1)+(a2+a3)) * 0.25f;   // 1/sqrt(16)
        if (sVcm[c]) a = NEGV;
        sSc[h*CC + c] = a;
    }
    __syncthreads();

    // ---- softmax: warp h owns head h ----
    {
        int h = warp;
        float v0 = sSc[h*CC + lane];
        float v1 = (lane < CC-32) ? sSc[h*CC + lane + 32] : -3e38f;
        float mx = fmaxf(v0, v1);
        #pragma unroll
        for (int o = 16; o > 0; o >>= 1)
            mx = fmaxf(mx, __shfl_xor_sync(0xffffffffu, mx, o));
        float e0 = expf(v0 - mx);
        float e1 = (lane < CC-32) ? expf(v1 - mx) : 0.f;
        float sm = e0 + e1;
        #pragma unroll
        for (int o = 16; o > 0; o >>= 1)
            sm += __shfl_xor_sync(0xffffffffu, sm, o);
        float inv = 1.f / sm;
        sAt[h*CC + lane] = e0 * inv;
        if (lane < CC-32) sAt[h*CC + lane + 32] = e1 * inv;
    }
    __syncthreads();

    // ---- a_ce[h][e]: 1024 outputs over 256 threads, 50 MACs ----
    #pragma unroll
    for (int k = 0; k < 4; k++) {
        int idx = t + 256*k;
        int h = idx >> 7, e = idx & 127;
        float a0=0.f,a1=0.f;
        #pragma unroll 5
        for (int c = 0; c < CC; c += 2) {
            a0 += sAt[h*CC + c  ] * sCET[e*CCP + c  ];
            a1 += sAt[h*CC + c+1] * sCET[e*CCP + c+1];
        }
        sAce[h*EE + e] = a0 + a1;
    }
    __syncthreads();

    // ---- glimpse[j=t2]: 128-MAC split-K over halves (h = j/16) ----
    {
        int h = t2 / DD;
        const int e0 = half*64;
        float a0=0.f,a1=0.f,a2=0.f,a3=0.f;
        #pragma unroll 4
        for (int e = 0; e < 64; e += 4) {
            a0 += sAce[h*EE + e0+e  ] * g_Wvf[(e0+e  )*EE + t2];
            a1 += sAce[h*EE + e0+e+1] * g_Wvf[(e0+e+1)*EE + t2];
            a2 += sAce[h*EE + e0+e+2] * g_Wvf[(e0+e+2)*EE + t2];
            a3 += sAce[h*EE + e0+e+3] * g_Wvf[(e0+e+3)*EE + t2];
        }
        sP2[half][t2] = (a0+a1)+(a2+a3);
    }
    __syncthreads();
    if (half == 0) sGl[t2] = sP2[0][t2] + sP2[1][t2];
    __syncthreads();

    // ---- w2[e=t2] = sum_j gl[j] * WoKs[j][e]: split-K over halves ----
    {
        const int j0 = half*64;
        float a0=0.f,a1=0.f,a2=0.f,a3=0.f;
        #pragma unroll 4
        for (int j = 0; j < 64; j += 4) {
            a0 += sGl[j0+j  ] * g_WoKs[(j0+j  )*EE + t2];
            a1 += sGl[j0+j+1] * g_WoKs[(j0+j+1)*EE + t2];
            a2 += sGl[j0+j+2] * g_WoKs[(j0+j+2)*EE + t2];
            a3 += sGl[j0+j+3] * g_WoKs[(j0+j+3)*EE + t2];
        }
        sP2[half][t2] = (a0+a1)+(a2+a3);
    }
    __syncthreads();
    if (half == 0) sW2[t2] = sP2[0][t2] + sP2[1][t2];
    __syncthreads();

    // ---- logit[c]: 50 outputs, split over 4 quarters of e ----
    {
        int c = t & 63, q4 = t >> 6;
        if (c < CC) {
            const int e0 = q4*32;
            float a0=0.f,a1=0.f;
            #pragma unroll 4
            for (int e = 0; e < 32; e += 2) {
                a0 += sCET[(e0+e  )*CCP + c] * sW2[e0+e  ];
                a1 += sCET[(e0+e+1)*CCP + c] * sW2[e0+e+1];
            }
            sLgP[q4][c] = a0 + a1;
        }
    }
    __syncthreads();
    if (t < CC) {
        float a = (sLgP[0][t] + sLgP[1][t]) + (sLgP[2][t] + sLgP[3][t]);
        a *= 0.08838834764831845f;     // 1/sqrt(128)
        a = tanhf(a) * 10.f;
        if (sVcm[t]) a = NEGV;
        sLg[t] = a;
    }
    __syncthreads();

    // ---- argmax (first-index ties) + logsumexp, warp 0 via shfl ----
    if (warp == 0) {
        float v0 = sLg[lane];
        float v1 = (lane < CC-32) ? sLg[lane + 32] : -3e38f;
        float v = v0; int ix = lane;
        if (v1 > v) { v = v1; ix = lane + 32; }
        #pragma unroll
        for (int o = 16; o > 0; o >>= 1) {
            float ov = __shfl_xor_sync(0xffffffffu, v, o);
            int   oi = __shfl_xor_sync(0xffffffffu, ix, o);
            if (ov > v || (ov == v && oi < ix)) { v = ov; ix = oi; }
        }
        float mx = v;
        float sm = expf(v0 - mx) + ((lane < CC-32) ? expf(v1 - mx) : 0.f);
        #pragma unroll
        for (int o = 16; o > 0; o >>= 1)
            sm += __shfl_xor_sync(0xffffffffu, sm, o);
        if (lane == 0) { sMax = mx; sLse = logf(sm); sArg = ix; }
    }
    __syncthreads();

    const int  guid = sArg;
    const bool isn  = isnew[b] != 0;
    const float ge  = sCET[t2*CCP + guid];

    const size_t OFF1 = (size_t)BB*4*EE;            // guid_embed_out
    const size_t OFF2 = OFF1 + (size_t)BB*EE;       // guid_out
    const size_t OFF3 = OFF2 + BB;                  // clu_prob

    float* ao = out + (size_t)b*4*EE;
    const float* ac = augc + (size_t)b*4*EE;
    if (half == 0) {
        ao[t2]        = isn ? sUC[t2]          : ac[t2];
        ao[2*EE + t2] = isn ? ge               : ac[2*EE + t2];
        out[OFF1 + (size_t)b*EE + t2] = isn ? ge : gein[b*EE + t2];
    } else {
        ao[EE + t2]   = isn ? sCtx[EE + t2]    : ac[EE + t2];
        ao[3*EE + t2] = isn ? sCtx[2*EE + t2]  : ac[3*EE + t2];
    }
    if (t == 0) out[OFF2 + b] = (float)(isn ? guid : guid_in[b]);
    if (t < CC) out[OFF3 + (size_t)b*CC + t] = isn ? (sLg[t] - sMax - sLse) : 0.f;
}

// ---------------------------------------------------------------------------
extern "C" void kernel_launch(void* const* d_in, const int* in_sizes, int n_in,
                              void* d_out, int out_size) {
    const float* depot = (const float*)d_in[0];
    const float* CE    = (const float*)d_in[1];
    const float* cur   = (const float*)d_in[2];
    const float* nodes = (const float*)d_in[3];
    const float* augc  = (const float*)d_in[4];
    const float* gein  = (const float*)d_in[5];
    const float* Wq    = (const float*)d_in[6];
    const float* Wk    = (const float*)d_in[7];
    const float* Wv    = (const float*)d_in[8];
    const float* Wks   = (const float*)d_in[9];
    const float* mWq   = (const float*)d_in[10];
    const float* mWk   = (const float*)d_in[11];
    const float* mWv   = (const float*)d_in[12];
    const float* Wo    = (const float*)d_in[13];
    const int* isnew   = (const int*)d_in[14];   // bool -> int32
    const int* mask    = (const int*)d_in[15];   // bool -> int32
    const int* cmask   = (const int*)d_in[16];   // bool -> int32
    const int* vcm     = (const int*)d_in[17];   // bool -> int32
    const int* guid    = (const int*)d_in[18];
    // d_in[19] = step (unused)

    dim3 gr(BB, SPLIT + 2);   // 8 reduce planes + 2 zero-smem prep planes
    k_pre<<<gr, 128>>>(nodes, mask, cmask, Wq, Wk, Wv, Wks, mWq, mWk, mWv);
    k_mid<<<EE + BB/8, 128>>>(Wo, cur, depot);   // 128 WoKs + 64 qcd blocks
    k_main<<<BB, 256>>>(depot, CE, cur, augc, gein, isnew, vcm, guid,
                        (float*)d_out);
}